// round 2
// baseline (speedup 1.0000x reference)
#include <cuda_runtime.h>
#include <cuda_bf16.h>

// MLPDecoder: logit[e] = relu([zu, zv, |zu-zv|] @ W1 + b1) @ W2 + b2
// Split: feat@W1 = zu@W1a + zv@W1b + |zu-zv|@W1c  (W1a=rows 0:128, W1b=128:256, W1c=256:384)
// Kernel1: AB[n] = [ z[n]@W1a , z[n]@W1b ]   (N x 256 scratch)
// Kernel2: per edge: t = AB[u][0:128] + AB[v][128:256] + |zu-zv|@W1c + b1; out = relu(t)@W2 + b2
// NOTE: edge_index arrives as int32 (JAX x64 disabled downcasts the requested int64).

#define N_NODES_MAX 100000
#define DIM 128
#define HID 128

// scratch: AB [N, 256] fp32  (102.4 MB, static device array per harness rules)
__device__ float g_AB[(size_t)N_NODES_MAX * 256];

typedef unsigned long long ull;

__device__ __forceinline__ ull pack2(float lo, float hi) {
    ull r;
    asm("mov.b64 %0, {%1, %2};" : "=l"(r) : "f"(lo), "f"(hi));
    return r;
}
__device__ __forceinline__ void unpack2(ull v, float& lo, float& hi) {
    asm("mov.b64 {%0, %1}, %2;" : "=f"(lo), "=f"(hi) : "l"(v));
}
__device__ __forceinline__ ull fma2(ull a, ull b, ull c) {
    ull d;
    asm("fma.rn.f32x2 %0, %1, %2, %3;" : "=l"(d) : "l"(a), "l"(b), "l"(c));
    return d;
}

// ---------------------------------------------------------------------------
// Kernel 1: AB = z @ [W1a | W1b]     M=N_nodes, N=256, K=128
// Block 256 threads = 8 warps, each warp computes 8 rows. Persistent grid.
// SMEM: sW [128][256] fp32 (128KB) + sZ packed (z,z) pairs [8 warps][8 rows][128] (64KB)
// ---------------------------------------------------------------------------
__global__ __launch_bounds__(256, 1) void precompute_ab_kernel(
    const float* __restrict__ z, const float* __restrict__ W1,
    float* __restrict__ AB, int N)
{
    extern __shared__ __align__(16) unsigned char smem_raw[];
    float* sW = (float*)smem_raw;                               // 128*256 floats
    ull*   sZ = (ull*)(smem_raw + 128 * 256 * sizeof(float));   // [8][8][128] packed

    const int tid  = threadIdx.x;
    const int warp = tid >> 5;
    const int lane = tid & 31;

    // Wab[k][j]: j<128 -> W1[k][j] ; j>=128 -> W1[128+k][j-128]
    for (int i = tid; i < 128 * 256; i += 256) {
        int k = i >> 8, j = i & 255;
        sW[i] = (j < 128) ? W1[k * 128 + j] : W1[(128 + k) * 128 + (j - 128)];
    }
    __syncthreads();

    ull* myZ = sZ + warp * 8 * 128;
    const int tiles = (N + 63) >> 6;

    for (int t = blockIdx.x; t < tiles; t += gridDim.x) {
        const int rowBase = (t << 6) + warp * 8;

        // load 8 z rows, pre-duplicated as (z,z) fp32x2 pairs
        #pragma unroll
        for (int r = 0; r < 8; r++) {
            int n = rowBase + r;
            float4 zv = make_float4(0.f, 0.f, 0.f, 0.f);
            if (n < N) zv = *(const float4*)(z + (size_t)n * DIM + lane * 4);
            myZ[r * 128 + lane * 4 + 0] = pack2(zv.x, zv.x);
            myZ[r * 128 + lane * 4 + 1] = pack2(zv.y, zv.y);
            myZ[r * 128 + lane * 4 + 2] = pack2(zv.z, zv.z);
            myZ[r * 128 + lane * 4 + 3] = pack2(zv.w, zv.w);
        }
        __syncwarp();

        ull aA0[8], aA1[8], aB0[8], aB1[8];
        #pragma unroll
        for (int r = 0; r < 8; r++) { aA0[r] = 0ull; aA1[r] = 0ull; aB0[r] = 0ull; aB1[r] = 0ull; }

        #pragma unroll 4
        for (int k = 0; k < 128; k++) {
            ulonglong2 wa = *(const ulonglong2*)(sW + k * 256 + lane * 4);
            ulonglong2 wb = *(const ulonglong2*)(sW + k * 256 + 128 + lane * 4);
            #pragma unroll
            for (int r = 0; r < 8; r++) {
                ull zz = myZ[r * 128 + k];
                aA0[r] = fma2(zz, wa.x, aA0[r]);
                aA1[r] = fma2(zz, wa.y, aA1[r]);
                aB0[r] = fma2(zz, wb.x, aB0[r]);
                aB1[r] = fma2(zz, wb.y, aB1[r]);
            }
        }

        #pragma unroll
        for (int r = 0; r < 8; r++) {
            int n = rowBase + r;
            if (n < N) {
                float4 oa, ob;
                unpack2(aA0[r], oa.x, oa.y); unpack2(aA1[r], oa.z, oa.w);
                unpack2(aB0[r], ob.x, ob.y); unpack2(aB1[r], ob.z, ob.w);
                *(float4*)(AB + (size_t)n * 256 + lane * 4) = oa;
                *(float4*)(AB + (size_t)n * 256 + 128 + lane * 4) = ob;
            }
        }
        __syncwarp();
    }
}

// ---------------------------------------------------------------------------
// Kernel 2: per-edge |zu-zv| @ W1c + combine + MLP head.
// Block 256 threads = 8 warps, each warp processes 8 edges per group.
// SMEM: sW1c [128][128] (64KB) + packed diff (d,d) [8 warps][8 edges][128] (64KB) + b1/W2
// ---------------------------------------------------------------------------
__global__ __launch_bounds__(256, 1) void edge_mlp_kernel(
    const float* __restrict__ z, const int* __restrict__ eidx,
    const float* __restrict__ W1, const float* __restrict__ b1,
    const float* __restrict__ W2, const float* __restrict__ b2,
    const float* __restrict__ AB, float* __restrict__ out, int E)
{
    extern __shared__ __align__(16) unsigned char smem_raw[];
    float* sW  = (float*)smem_raw;                              // W1c 128*128
    ull*   sd  = (ull*)(smem_raw + 65536);                      // [8][8][128] packed diffs
    float* sb1 = (float*)(smem_raw + 65536 + 65536);            // 128
    float* sw2 = sb1 + 128;                                     // 128

    const int tid  = threadIdx.x;
    const int warp = tid >> 5;
    const int lane = tid & 31;

    // W1c[k][j] = W1[(256+k)*128 + j] -> contiguous block starting at 32768
    for (int i = tid; i < 128 * 128; i += 256) sW[i] = W1[32768 + i];
    if (tid < 128) { sb1[tid] = b1[tid]; sw2[tid] = W2[tid]; }
    __syncthreads();

    ull* myd = sd + warp * 8 * 128;
    const float4 b14 = *(const float4*)(sb1 + lane * 4);
    const float4 w24 = *(const float4*)(sw2 + lane * 4);
    const float bias2 = b2[0];

    const int ngroups = (E + 7) >> 3;
    const int nw = gridDim.x * 8;

    for (int g = blockIdx.x * 8 + warp; g < ngroups; g += nw) {
        const int base = g << 3;
        ull acc0[8], acc1[8];

        #pragma unroll
        for (int e = 0; e < 8; e++) {
            int ei = base + e;
            float4 dd = make_float4(0.f, 0.f, 0.f, 0.f);
            float4 ab = make_float4(0.f, 0.f, 0.f, 0.f);
            if (ei < E) {
                size_t u = (size_t)(unsigned)eidx[ei];
                size_t v = (size_t)(unsigned)eidx[(size_t)E + ei];
                float4 zu = __ldg((const float4*)(z + u * DIM) + lane);
                float4 zv = __ldg((const float4*)(z + v * DIM) + lane);
                dd.x = fabsf(zu.x - zv.x); dd.y = fabsf(zu.y - zv.y);
                dd.z = fabsf(zu.z - zv.z); dd.w = fabsf(zu.w - zv.w);
                float4 a4 = __ldg((const float4*)(AB + u * 256) + lane);
                float4 b4 = __ldg((const float4*)(AB + v * 256 + 128) + lane);
                ab.x = a4.x + b4.x; ab.y = a4.y + b4.y;
                ab.z = a4.z + b4.z; ab.w = a4.w + b4.w;
            }
            myd[e * 128 + lane * 4 + 0] = pack2(dd.x, dd.x);
            myd[e * 128 + lane * 4 + 1] = pack2(dd.y, dd.y);
            myd[e * 128 + lane * 4 + 2] = pack2(dd.z, dd.z);
            myd[e * 128 + lane * 4 + 3] = pack2(dd.w, dd.w);
            acc0[e] = pack2(ab.x, ab.y);
            acc1[e] = pack2(ab.z, ab.w);
        }
        __syncwarp();

        #pragma unroll 8
        for (int k = 0; k < 128; k++) {
            ulonglong2 w = *(const ulonglong2*)(sW + k * 128 + lane * 4);
            #pragma unroll
            for (int e = 0; e < 8; e++) {
                ull d2 = myd[e * 128 + k];
                acc0[e] = fma2(d2, w.x, acc0[e]);
                acc1[e] = fma2(d2, w.y, acc1[e]);
            }
        }

        #pragma unroll
        for (int e = 0; e < 8; e++) {
            float t0, t1, t2, t3;
            unpack2(acc0[e], t0, t1);
            unpack2(acc1[e], t2, t3);
            t0 = fmaxf(t0 + b14.x, 0.f);
            t1 = fmaxf(t1 + b14.y, 0.f);
            t2 = fmaxf(t2 + b14.z, 0.f);
            t3 = fmaxf(t3 + b14.w, 0.f);
            float p = t0 * w24.x + t1 * w24.y + t2 * w24.z + t3 * w24.w;
            p += __shfl_xor_sync(0xFFFFFFFFu, p, 16);
            p += __shfl_xor_sync(0xFFFFFFFFu, p, 8);
            p += __shfl_xor_sync(0xFFFFFFFFu, p, 4);
            p += __shfl_xor_sync(0xFFFFFFFFu, p, 2);
            p += __shfl_xor_sync(0xFFFFFFFFu, p, 1);
            if (lane == 0 && base + e < E) out[base + e] = p + bias2;
        }
        __syncwarp();
    }
}

extern "C" void kernel_launch(void* const* d_in, const int* in_sizes, int n_in,
                              void* d_out, int out_size) {
    const float* z    = (const float*)d_in[0];
    const int*   eidx = (const int*)d_in[1];     // int32 on the wire (JAX x64 off)
    const float* W1   = (const float*)d_in[2];
    const float* b1   = (const float*)d_in[3];
    const float* W2   = (const float*)d_in[4];
    const float* b2   = (const float*)d_in[5];
    float*       out  = (float*)d_out;

    const int N = in_sizes[0] / DIM;       // 100000
    const int E = in_sizes[1] / 2;         // 500000

    float* AB = nullptr;
    cudaGetSymbolAddress((void**)&AB, g_AB);

    const int k1_smem = 128 * 256 * 4 + 8 * 8 * 128 * 8;            // 196608
    const int k2_smem = 128 * 128 * 4 + 8 * 8 * 128 * 8 + 256 * 4;  // 132096
    cudaFuncSetAttribute(precompute_ab_kernel, cudaFuncAttributeMaxDynamicSharedMemorySize, k1_smem);
    cudaFuncSetAttribute(edge_mlp_kernel,      cudaFuncAttributeMaxDynamicSharedMemorySize, k2_smem);

    precompute_ab_kernel<<<148, 256, k1_smem>>>(z, W1, AB, N);
    edge_mlp_kernel<<<148, 256, k2_smem>>>(z, eidx, W1, b1, W2, b2, AB, out, E);
}